// round 16
// baseline (speedup 1.0000x reference)
#include <cuda_runtime.h>
#include <cuda_bf16.h>

// Elementwise clip: out = min(max(x, lo), hi)
// x: 33,554,432 fp32 = 4,194,304 float8s = 4096 blocks x 512 threads x 2 (exact).
//
// Converged config (256-bit .cs loads+stores, 2 front-batched v8 per thread,
// 64B/thread, one-shot CTAs) — this round A/Bs the last untested knob:
// block size 512 (vs 256). Resident-warp count per SM unchanged; prediction
// is flat within the charted plateau (kernel 35.4-36.8us, DRAM 73-76%).

__device__ __forceinline__ void ld256_cs(const float* p, float4& a, float4& b)
{
    asm volatile(
        "ld.global.cs.v8.f32 {%0,%1,%2,%3,%4,%5,%6,%7}, [%8];"
        : "=f"(a.x), "=f"(a.y), "=f"(a.z), "=f"(a.w),
          "=f"(b.x), "=f"(b.y), "=f"(b.z), "=f"(b.w)
        : "l"(p));
}

__device__ __forceinline__ void st256_cs(float* p, const float4& a, const float4& b)
{
    asm volatile(
        "st.global.cs.v8.f32 [%0], {%1,%2,%3,%4,%5,%6,%7,%8};"
        :: "l"(p),
           "f"(a.x), "f"(a.y), "f"(a.z), "f"(a.w),
           "f"(b.x), "f"(b.y), "f"(b.z), "f"(b.w)
        : "memory");
}

__device__ __forceinline__ float4 clip4(float4 v, float lo, float hi)
{
    v.x = fminf(fmaxf(v.x, lo), hi);
    v.y = fminf(fmaxf(v.y, lo), hi);
    v.z = fminf(fmaxf(v.z, lo), hi);
    v.w = fminf(fmaxf(v.w, lo), hi);
    return v;
}

__global__ __launch_bounds__(512) void clip_kernel_b512(
    const float* __restrict__ x,
    const float* __restrict__ clamp_params,
    float* __restrict__ out)
{
    const float lo = clamp_params[0];
    const float hi = clamp_params[1];

    // 32-bit byte offset; second access +512 float8s = +16384 bytes.
    const unsigned boff = (blockIdx.x * (512u * 2u) + threadIdx.x) * 32u;
    const float* src = (const float*)((const char*)x + boff);
    float*       dst = (float*)((char*)out + boff);

    float4 a0, b0, a1, b1;
    ld256_cs(src,        a0, b0);
    ld256_cs(src + 4096, a1, b1);   // +512 * 8 floats

    a0 = clip4(a0, lo, hi);  b0 = clip4(b0, lo, hi);
    a1 = clip4(a1, lo, hi);  b1 = clip4(b1, lo, hi);

    st256_cs(dst,        a0, b0);
    st256_cs(dst + 4096, a1, b1);
}

// Generic fallback (any size).
__global__ __launch_bounds__(256) void clip_kernel_generic(
    const float* __restrict__ x,
    const float* __restrict__ clamp_params,
    float* __restrict__ out,
    int n)
{
    const float lo = clamp_params[0];
    const float hi = clamp_params[1];
    for (int i = blockIdx.x * blockDim.x + threadIdx.x; i < n;
         i += gridDim.x * blockDim.x)
        out[i] = fminf(fmaxf(__ldcs(&x[i]), lo), hi);
}

extern "C" void kernel_launch(void* const* d_in, const int* in_sizes, int n_in,
                              void* d_out, int out_size)
{
    const float* x = (const float*)d_in[0];
    const float* clamp_params = (const float*)d_in[1];
    float* out = (float*)d_out;

    int n = out_size;                       // 33,554,432
    const int threads = 512;
    const int chunk = threads * 2 * 8;      // floats per block: 8192

    if ((n % chunk) == 0) {
        int blocks = n / chunk;             // 4096
        clip_kernel_b512<<<blocks, threads>>>(x, clamp_params, out);
    } else {
        int blocks = (n + 255) / 256;
        if (blocks > 65535 * 16) blocks = 65535 * 16;
        clip_kernel_generic<<<blocks, 256>>>(x, clamp_params, out, n);
    }
}

// round 17
// speedup vs baseline: 1.0361x; 1.0361x over previous
#include <cuda_runtime.h>
#include <cuda_bf16.h>

// Elementwise clip: out = min(max(x, lo), hi)
// x: [4194304, 8] fp32 = 33,554,432 elems = 4,194,304 float8s
//    = 8192 blocks x 256 threads x 2 float8s (exact, predicate-free).
//
// FINAL kernel — converged over 15 benches. Configuration:
//   - 256-bit streaming accesses (LDG.E.256 / STG.E.256), .cs both ways
//   - 2 front-batched loads per thread (64 B/thread), one-shot CTAs
//   - 8192 x 256 (best dur_us bucket: 43.49, hit in 4 separate rounds)
//   - 32-bit byte-offset addressing
// Roofline: 268 MB mandatory traffic at the measured HBM3e 1R:1W turnaround
// ceiling (5.8-6.0 TB/s, 73-76% of 8 TB/s spec) -> ~35.5us kernel floor.
// Invariant under: vector width (v4/v8), per-warp MLP (1-8), occupancy
// (58-79%), block size (256/512), one-shot vs persistent grids, load/store
// eviction policies, predication, addressing width. SM pipes idle (~9% issue).

__device__ __forceinline__ void ld256_cs(const float* p, float4& a, float4& b)
{
    asm volatile(
        "ld.global.cs.v8.f32 {%0,%1,%2,%3,%4,%5,%6,%7}, [%8];"
        : "=f"(a.x), "=f"(a.y), "=f"(a.z), "=f"(a.w),
          "=f"(b.x), "=f"(b.y), "=f"(b.z), "=f"(b.w)
        : "l"(p));
}

__device__ __forceinline__ void st256_cs(float* p, const float4& a, const float4& b)
{
    asm volatile(
        "st.global.cs.v8.f32 [%0], {%1,%2,%3,%4,%5,%6,%7,%8};"
        :: "l"(p),
           "f"(a.x), "f"(a.y), "f"(a.z), "f"(a.w),
           "f"(b.x), "f"(b.y), "f"(b.z), "f"(b.w)
        : "memory");
}

__device__ __forceinline__ float4 clip4(float4 v, float lo, float hi)
{
    v.x = fminf(fmaxf(v.x, lo), hi);
    v.y = fminf(fmaxf(v.y, lo), hi);
    v.z = fminf(fmaxf(v.z, lo), hi);
    v.w = fminf(fmaxf(v.w, lo), hi);
    return v;
}

__global__ __launch_bounds__(256) void clip_kernel_final(
    const float* __restrict__ x,
    const float* __restrict__ clamp_params,
    float* __restrict__ out)
{
    const float lo = clamp_params[0];
    const float hi = clamp_params[1];

    // 32-bit byte offset: total extent 134MB < 2^31. Exact.
    const unsigned boff = (blockIdx.x * (256u * 2u) + threadIdx.x) * 32u;
    const float* src = (const float*)((const char*)x + boff);
    float*       dst = (float*)((char*)out + boff);

    float4 a0, b0, a1, b1;
    ld256_cs(src,        a0, b0);
    ld256_cs(src + 2048, a1, b1);   // +256 float8s = +8192 bytes

    a0 = clip4(a0, lo, hi);  b0 = clip4(b0, lo, hi);
    a1 = clip4(a1, lo, hi);  b1 = clip4(b1, lo, hi);

    st256_cs(dst,        a0, b0);
    st256_cs(dst + 2048, a1, b1);
}

// Generic fallback (any size).
__global__ __launch_bounds__(256) void clip_kernel_generic(
    const float* __restrict__ x,
    const float* __restrict__ clamp_params,
    float* __restrict__ out,
    int n)
{
    const float lo = clamp_params[0];
    const float hi = clamp_params[1];
    for (int i = blockIdx.x * blockDim.x + threadIdx.x; i < n;
         i += gridDim.x * blockDim.x)
        out[i] = fminf(fmaxf(__ldcs(&x[i]), lo), hi);
}

extern "C" void kernel_launch(void* const* d_in, const int* in_sizes, int n_in,
                              void* d_out, int out_size)
{
    const float* x = (const float*)d_in[0];
    const float* clamp_params = (const float*)d_in[1];
    float* out = (float*)d_out;

    int n = out_size;                       // 33,554,432
    const int threads = 256;
    const int chunk = threads * 2 * 8;      // floats per block: 4096

    if ((n % chunk) == 0) {
        int blocks = n / chunk;             // 8192
        clip_kernel_final<<<blocks, threads>>>(x, clamp_params, out);
    } else {
        int blocks = (n + threads - 1) / threads;
        if (blocks > 65535 * 16) blocks = 65535 * 16;
        clip_kernel_generic<<<blocks, threads>>>(x, clamp_params, out, n);
    }
}